// round 15
// baseline (speedup 1.0000x reference)
#include <cuda_runtime.h>
#include <cuda_fp16.h>
#include <cstdint>

#define NN   256
#define TT   300
#define NV   25
#define NCH  75
#define NP   (NV * TT)            // 7500
#define MTILE 128                 // points per tile
#define NTPB  60                  // tiles per batch row
#define NTILES (NN * NTPB)        // 15360
#define THREADS 256
#define GRID_MAIN 296             // 2 CTAs per SM, persistent

// parent joint (0-indexed)
__constant__ int c_par[NV] = {1,20,20,2,20,4,5,6,20,8,9,10,0,12,13,14,0,16,17,18,20,22,7,24,11};

// folded BN affine per channel (index = c*25+v)
__device__ float g_sc1[NCH], g_sh1[NCH], g_sc2[NCH], g_sh2[NCH];

// bone / t_bone scratch: [n][ch 0..5][p]
__device__ float g_bone[(size_t)NN * 6 * NP];

// stats partials
#define SBLK 1024
__device__ float g_ps1[NCH * 3 * SBLK];
__device__ float g_pq1[NCH * 3 * SBLK];
__device__ float g_ps2[NCH * 3 * SBLK];
__device__ float g_pq2[NCH * 3 * SBLK];

__device__ __forceinline__ uint32_t s2u(const void* p) {
    uint32_t a;
    asm("{ .reg .u64 t; cvta.to.shared.u64 t, %1; cvt.u32.u64 %0, t; }" : "=r"(a) : "l"(p));
    return a;
}

__device__ __forceinline__ void ldsm4(uint32_t* r, uint32_t addr) {
    asm volatile("ldmatrix.sync.aligned.m8n8.x4.shared.b16 {%0,%1,%2,%3}, [%4];"
                 : "=r"(r[0]), "=r"(r[1]), "=r"(r[2]), "=r"(r[3]) : "r"(addr));
}

__device__ __forceinline__ void mma16816(float* d, const uint32_t* a, uint32_t b0, uint32_t b1) {
    asm volatile(
        "mma.sync.aligned.m16n8k16.row.col.f32.f16.f16.f32 "
        "{%0,%1,%2,%3}, {%4,%5,%6,%7}, {%8,%9}, {%0,%1,%2,%3};"
        : "+f"(d[0]), "+f"(d[1]), "+f"(d[2]), "+f"(d[3])
        : "r"(a[0]), "r"(a[1]), "r"(a[2]), "r"(a[3]), "r"(b0), "r"(b1));
}

// ---------------------------------------------------------------------------
// stats + bone precompute (div-free, padded smem): grid (4, 256), 256 threads
// ---------------------------------------------------------------------------
__global__ __launch_bounds__(256) void stats1(const float* __restrict__ x) {
    __shared__ float rows[76][77];     // 77 stride: conflict-free column reads
    int tc = blockIdx.x, n = blockIdx.y;
    int t0 = tc * 75;
    int tid = threadIdx.x;

    {
        int r = tid / NCH, c = tid - r * NCH;
        const float* xr = x + (size_t)n * TT * NCH;
        for (int i = tid; i < 76 * NCH; i += 256) {
            int t = t0 + r;
            rows[r][c] = (t < TT) ? xr[(size_t)t * NCH + c] : 0.0f;
            c += 31; r += 3; if (c >= NCH) { c -= NCH; r += 1; }
        }
    }
    __syncthreads();

    {
        float* bp = g_bone + (size_t)n * 6 * NP;
        int ch = tid / 75, r = tid - ch * 75;
        int c25 = ch / NV, v = ch - c25 * NV;
        for (int i = tid; i < 75 * 75; i += 256) {
            int ci = v * 3 + c25, pi = c_par[v] * 3 + c25;
            float b = rows[r][ci] - rows[r][pi];
            float d = 0.0f;
            if (t0 + r < TT - 1) d = (rows[r + 1][ci] - rows[r + 1][pi]) - b;
            size_t pidx = (size_t)v * TT + t0 + r;
            bp[(size_t)c25 * NP + pidx]       = b;
            bp[(size_t)(3 + c25) * NP + pidx] = d;
            r += 31; v += 3;
            if (r >= 75) { r -= 75; v += 1; }
            if (v >= NV) { v -= NV; c25 += 1; }
        }
    }

    int g = tid / NCH;
    int ch = tid - g * NCH;
    if (g < 3) {
        int c = ch / NV, v = ch - c * NV;
        int ci = v * 3 + c, pi = c_par[v] * 3 + c;
        float s1 = 0, q1 = 0, s2 = 0, q2 = 0;
        for (int r = g; r < 75; r += 3) {
            float b = rows[r][ci] - rows[r][pi];
            s1 += b; q1 += b * b;
            if (t0 + r < TT - 1) {
                float d = (rows[r + 1][ci] - rows[r + 1][pi]) - b;
                s2 += d; q2 += d * d;
            }
        }
        int idx = (ch * 3 + g) * SBLK + (tc * NN + n);
        g_ps1[idx] = s1; g_pq1[idx] = q1;
        g_ps2[idx] = s2; g_pq2[idx] = q2;
    }
}

__global__ __launch_bounds__(256) void stats2(
    const float* __restrict__ g1, const float* __restrict__ b1,
    const float* __restrict__ g2, const float* __restrict__ b2)
{
    int ch = blockIdx.x;
    int tid = threadIdx.x;
    float s1 = 0, q1 = 0, s2 = 0, q2 = 0;
    for (int g = 0; g < 3; g++) {
        int base = (ch * 3 + g) * SBLK;
        for (int i = tid; i < SBLK; i += 256) {
            s1 += g_ps1[base + i]; q1 += g_pq1[base + i];
            s2 += g_ps2[base + i]; q2 += g_pq2[base + i];
        }
    }
    __shared__ float red[4][256];
    red[0][tid] = s1; red[1][tid] = q1; red[2][tid] = s2; red[3][tid] = q2;
    __syncthreads();
    for (int s = 128; s > 0; s >>= 1) {
        if (tid < s) {
            #pragma unroll
            for (int j = 0; j < 4; j++) red[j][tid] += red[j][tid + s];
        }
        __syncthreads();
    }
    if (tid == 0) {
        const float inv = 1.0f / (float)(NN * TT);
        float m1 = red[0][0] * inv;
        float v1 = red[1][0] * inv - m1 * m1;
        float sc1 = rsqrtf(v1 + 1e-5f) * g1[ch];
        g_sc1[ch] = sc1;
        g_sh1[ch] = b1[ch] - m1 * sc1;
        float m2 = red[2][0] * inv;
        float v2 = red[3][0] * inv - m2 * m2;
        float sc2 = rsqrtf(v2 + 1e-5f) * g2[ch];
        g_sc2[ch] = sc2;
        g_sh2[ch] = b2[ch] - m2 * sc2;
    }
}

// ---------------------------------------------------------------------------
// main kernel: persistent CTAs; m32 x (n32 x 2) warp tile; register-prefetched
// bone loads; warp-local zy exchange => TWO block barriers per tile.
// ---------------------------------------------------------------------------
#define ASTR 144                       // A row stride bytes
#define BSTR 144                       // B row stride bytes
#define OFF_A1  0
#define OFF_A2  (OFF_A1 + MTILE * ASTR)
#define OFF_B   (OFF_A2 + MTILE * ASTR)
#define OFF_ZS  (OFF_B + 128 * BSTR)   // per-warp zy slabs: 8 x 512 B
#define OFF_BB1 (OFF_ZS + 8 * 512)
#define OFF_BB2 (OFF_BB1 + 256)
#define SMEM_SZ (OFF_BB2 + 256)

extern __shared__ char smem[];

__global__ __launch_bounds__(THREADS, 2) void main_mma(
    const float* __restrict__ w1a, const float* __restrict__ b1a,
    const float* __restrict__ w1b, const float* __restrict__ b1b,
    const float* __restrict__ w2a, const float* __restrict__ b2a,
    const float* __restrict__ w2b, const float* __restrict__ b2b,
    float* __restrict__ out)
{
    const int tid  = threadIdx.x;
    const int wid  = tid >> 5, lane = tid & 31;

    // ---- one-time staging: fused weight tile (fp16) + biases ----
    for (int i = tid; i < 64 * 64; i += THREADS) {
        int o = i >> 6, h = i & 63;
        *(__half*)(smem + OFF_B + o * BSTR + h * 2)        = __float2half_rn(w1b[i]);
        *(__half*)(smem + OFF_B + (o + 64) * BSTR + h * 2) = __float2half_rn(w2b[i]);
    }
    if (tid < 64) {
        ((float*)(smem + OFF_BB1))[tid] = b1b[tid];
    } else if (tid < 128) {
        ((float*)(smem + OFF_BB2))[tid - 64] = b2b[tid - 64];
    }

    // ---- layer-1 weights in registers (thread owns o-pair = lane) ----
    const int o0 = lane * 2, o1 = lane * 2 + 1;
    const float4 wp1 = make_float4(w1a[o0*3], w1a[o0*3+1], w1a[o0*3+2], b1a[o0]);
    const float4 wq1 = make_float4(w1a[o1*3], w1a[o1*3+1], w1a[o1*3+2], b1a[o1]);
    const float4 wp2 = make_float4(w2a[o0*3], w2a[o0*3+1], w2a[o0*3+2], b2a[o0]);
    const float4 wq2 = make_float4(w2a[o1*3], w2a[o1*3+1], w2a[o1*3+2], b2a[o1]);

    const uint32_t sA1 = s2u(smem + OFF_A1), sA2 = s2u(smem + OFF_A2);
    const uint32_t sB  = s2u(smem + OFF_B);

    // MMA warp tiling: pg = point-group (32 pts), oh = o-half (32 outs)
    const int pg = wid & 3, oh = wid >> 2;
    const uint32_t arow = (uint32_t)(pg * 32 + (lane & 15)) * ASTR + (lane >> 4) * 16;
    const uint32_t brow1 = (uint32_t)(oh * 32 + (lane & 7)) * BSTR + (lane >> 3) * 16;
    const uint32_t brow2 = brow1 + 64 * BSTR;

    // ---- warp-local bone prefetch state ----
    // lane<16: bone xyz for point wid*16+lane; lane>=16: tbone xyz for wid*16+(lane-16)
    const int pl  = lane & 15;
    const int sel = lane >> 4;
    float pc0 = 0, pc1 = 0, pc2 = 0;
    int   pvv = 0;

    // prologue: prefetch this CTA's first tile
    {
        const int t0t = blockIdx.x;
        if (t0t < NTILES) {
            const int n0   = t0t / NTPB;
            const int tp00 = (t0t - n0 * NTPB) * MTILE;
            const int pp   = tp00 + wid * 16 + pl;
            const int pgc  = (pp < NP) ? pp : (NP - 1);
            pvv = pgc / TT;
            const float* bb = g_bone + (size_t)n0 * 6 * NP + (sel ? 3 * NP : 0) + pgc;
            pc0 = bb[0]; pc1 = bb[NP]; pc2 = bb[2 * NP];
        }
    }

    for (int t = blockIdx.x; t < NTILES; t += GRID_MAIN) {
        const int n   = t / NTPB;
        const int tp0 = (t - n * NTPB) * MTILE;

        // bar 1: staging visible (first iter); A-tile reuse safety (later)
        __syncthreads();

        // ---- warp-local zy compute from prefetched registers -> warp slab ----
        {
            const int v = pvv;
            const float* sc = sel ? g_sc2 : g_sc1;
            const float* sh = sel ? g_sh2 : g_sh1;
            float e0 = sc[v]          * pc0 + sh[v];
            float e1 = sc[NV + v]     * pc1 + sh[NV + v];
            float e2 = sc[2 * NV + v] * pc2 + sh[2 * NV + v];
            *(float4*)(smem + OFF_ZS + wid * 512 + pl * 32 + sel * 16) =
                make_float4(e0, e1, e2, 0.f);
        }
        __syncwarp();

        // ---- H phase: thread = o-pair (lane), warp covers its 16 points ----
        #pragma unroll
        for (int i = 0; i < 16; i++) {
            const int p = wid * 16 + i;
            float4 z = *(const float4*)(smem + OFF_ZS + wid * 512 + i * 32);
            float4 y = *(const float4*)(smem + OFF_ZS + wid * 512 + i * 32 + 16);
            float h0 = fmaxf(fmaf(wp1.x, z.x, fmaf(wp1.y, z.y, fmaf(wp1.z, z.z, wp1.w))), 0.0f);
            float h1 = fmaxf(fmaf(wq1.x, z.x, fmaf(wq1.y, z.y, fmaf(wq1.z, z.z, wq1.w))), 0.0f);
            uint32_t pk;
            asm("cvt.rn.f16x2.f32 %0, %1, %2;" : "=r"(pk) : "f"(h1), "f"(h0));
            *(uint32_t*)(smem + OFF_A1 + p * ASTR + lane * 4) = pk;

            float g0 = fmaxf(fmaf(wp2.x, y.x, fmaf(wp2.y, y.y, fmaf(wp2.z, y.z, wp2.w))), 0.0f);
            float g1 = fmaxf(fmaf(wq2.x, y.x, fmaf(wq2.y, y.y, fmaf(wq2.z, y.z, wq2.w))), 0.0f);
            asm("cvt.rn.f16x2.f32 %0, %1, %2;" : "=r"(pk) : "f"(g1), "f"(g0));
            *(uint32_t*)(smem + OFF_A2 + p * ASTR + lane * 4) = pk;
        }
        // bar 2: A tiles ready for MMA
        __syncthreads();

        // ---- prefetch NEXT tile's bone values (in flight through MMA) ----
        {
            const int tn = t + GRID_MAIN;
            if (tn < NTILES) {
                const int nn_  = tn / NTPB;
                const int tpn  = (tn - nn_ * NTPB) * MTILE;
                const int pp   = tpn + wid * 16 + pl;
                const int pgc  = (pp < NP) ? pp : (NP - 1);
                pvv = pgc / TT;
                const float* bb = g_bone + (size_t)nn_ * 6 * NP + (sel ? 3 * NP : 0) + pgc;
                pc0 = bb[0]; pc1 = bb[NP]; pc2 = bb[2 * NP];
            }
        }

        // ---- MMA phase: warp = m32 x n32 x 2 branches ----
        float a1[2][4][4], a2[2][4][4];
        #pragma unroll
        for (int mt = 0; mt < 2; mt++)
            #pragma unroll
            for (int nt = 0; nt < 4; nt++)
                #pragma unroll
                for (int q = 0; q < 4; q++) { a1[mt][nt][q] = 0.f; a2[mt][nt][q] = 0.f; }

        #pragma unroll
        for (int kcp = 0; kcp < 2; kcp++) {
            uint32_t af[2][2][4];
            // ---- branch 1 ----
            #pragma unroll
            for (int mt = 0; mt < 2; mt++)
                #pragma unroll
                for (int k2 = 0; k2 < 2; k2++)
                    ldsm4(af[mt][k2], sA1 + arow + (uint32_t)mt * 16 * ASTR + (kcp * 2 + k2) * 32);
            #pragma unroll
            for (int nt = 0; nt < 4; nt++) {
                uint32_t bf[4];
                ldsm4(bf, sB + brow1 + (uint32_t)nt * 8 * BSTR + kcp * 64);
                #pragma unroll
                for (int k2 = 0; k2 < 2; k2++)
                    #pragma unroll
                    for (int mt = 0; mt < 2; mt++)
                        mma16816(a1[mt][nt], af[mt][k2], bf[2*k2], bf[2*k2+1]);
            }
            // ---- branch 2 ----
            #pragma unroll
            for (int mt = 0; mt < 2; mt++)
                #pragma unroll
                for (int k2 = 0; k2 < 2; k2++)
                    ldsm4(af[mt][k2], sA2 + arow + (uint32_t)mt * 16 * ASTR + (kcp * 2 + k2) * 32);
            #pragma unroll
            for (int nt = 0; nt < 4; nt++) {
                uint32_t bf[4];
                ldsm4(bf, sB + brow2 + (uint32_t)nt * 8 * BSTR + kcp * 64);
                #pragma unroll
                for (int k2 = 0; k2 < 2; k2++)
                    #pragma unroll
                    for (int mt = 0; mt < 2; mt++)
                        mma16816(a2[mt][nt], af[mt][k2], bf[2*k2], bf[2*k2+1]);
            }
        }

        // ---- epilogue: bias + relu + sum, direct STG ----
        {
            const float* bb1 = (const float*)(smem + OFF_BB1);
            const float* bb2 = (const float*)(smem + OFF_BB2);
            float* ob = out + (size_t)n * 64 * NP;
            #pragma unroll
            for (int mt = 0; mt < 2; mt++) {
                const int r0 = tp0 + pg * 32 + mt * 16 + (lane >> 2);
                #pragma unroll
                for (int nt = 0; nt < 4; nt++) {
                    const int oc = oh * 32 + nt * 8 + (lane & 3) * 2;
                    float u0 = bb1[oc], u1 = bb1[oc + 1];
                    float w0 = bb2[oc], w1 = bb2[oc + 1];
                    if (r0 < NP) {
                        ob[(size_t)oc * NP + r0]       = fmaxf(a1[mt][nt][0] + u0, 0.f) + fmaxf(a2[mt][nt][0] + w0, 0.f);
                        ob[(size_t)(oc + 1) * NP + r0] = fmaxf(a1[mt][nt][1] + u1, 0.f) + fmaxf(a2[mt][nt][1] + w1, 0.f);
                    }
                    if (r0 + 8 < NP) {
                        ob[(size_t)oc * NP + r0 + 8]       = fmaxf(a1[mt][nt][2] + u0, 0.f) + fmaxf(a2[mt][nt][2] + w0, 0.f);
                        ob[(size_t)(oc + 1) * NP + r0 + 8] = fmaxf(a1[mt][nt][3] + u1, 0.f) + fmaxf(a2[mt][nt][3] + w1, 0.f);
                    }
                }
            }
        }
    }
}

// ---------------------------------------------------------------------------
extern "C" void kernel_launch(void* const* d_in, const int* in_sizes, int n_in,
                              void* d_out, int out_size)
{
    const float* x   = (const float*)d_in[0];
    const float* g1  = (const float*)d_in[1];
    const float* b1g = (const float*)d_in[2];
    const float* w1a = (const float*)d_in[3];
    const float* b1a = (const float*)d_in[4];
    const float* w1b = (const float*)d_in[5];
    const float* b1b = (const float*)d_in[6];
    const float* g2  = (const float*)d_in[7];
    const float* b2g = (const float*)d_in[8];
    const float* w2a = (const float*)d_in[9];
    const float* b2a = (const float*)d_in[10];
    const float* w2b = (const float*)d_in[11];
    const float* b2b = (const float*)d_in[12];
    float* out = (float*)d_out;

    stats1<<<dim3(4, NN), 256>>>(x);
    stats2<<<NCH, 256>>>(g1, b1g, g2, b2g);

    cudaFuncSetAttribute(main_mma, cudaFuncAttributeMaxDynamicSharedMemorySize, SMEM_SZ);
    main_mma<<<GRID_MAIN, THREADS, SMEM_SZ>>>(
        w1a, b1a, w1b, b1b, w2a, b2a, w2b, b2b, out);
}

// round 16
// speedup vs baseline: 1.0454x; 1.0454x over previous
#include <cuda_runtime.h>
#include <cuda_fp16.h>
#include <cstdint>

#define NN   256
#define TT   300
#define NV   25
#define NCH  75
#define NP   (NV * TT)            // 7500
#define MTILE 128                 // points per tile
#define NTPB  60                  // tiles per batch row
#define NTILES (NN * NTPB)        // 15360
#define THREADS 256
#define GRID_MAIN 296             // 2 CTAs per SM, persistent

// parent joint (0-indexed)
__constant__ int c_par[NV] = {1,20,20,2,20,4,5,6,20,8,9,10,0,12,13,14,0,16,17,18,20,22,7,24,11};

// folded BN affine per channel (index = c*25+v)
__device__ float g_sc1[NCH], g_sh1[NCH], g_sc2[NCH], g_sh2[NCH];

// bone / t_bone scratch: [n][ch 0..5][p]
__device__ float g_bone[(size_t)NN * 6 * NP];

// stats partials
#define SBLK 1024
__device__ float g_ps1[NCH * 3 * SBLK];
__device__ float g_pq1[NCH * 3 * SBLK];
__device__ float g_ps2[NCH * 3 * SBLK];
__device__ float g_pq2[NCH * 3 * SBLK];

__device__ __forceinline__ uint32_t s2u(const void* p) {
    uint32_t a;
    asm("{ .reg .u64 t; cvta.to.shared.u64 t, %1; cvt.u32.u64 %0, t; }" : "=r"(a) : "l"(p));
    return a;
}

__device__ __forceinline__ void ldsm4(uint32_t* r, uint32_t addr) {
    asm volatile("ldmatrix.sync.aligned.m8n8.x4.shared.b16 {%0,%1,%2,%3}, [%4];"
                 : "=r"(r[0]), "=r"(r[1]), "=r"(r[2]), "=r"(r[3]) : "r"(addr));
}

__device__ __forceinline__ void mma16816(float* d, const uint32_t* a, uint32_t b0, uint32_t b1) {
    asm volatile(
        "mma.sync.aligned.m16n8k16.row.col.f32.f16.f16.f32 "
        "{%0,%1,%2,%3}, {%4,%5,%6,%7}, {%8,%9}, {%0,%1,%2,%3};"
        : "+f"(d[0]), "+f"(d[1]), "+f"(d[2]), "+f"(d[3])
        : "r"(a[0]), "r"(a[1]), "r"(a[2]), "r"(a[3]), "r"(b0), "r"(b1));
}

// ---------------------------------------------------------------------------
// stats + bone precompute (div-free, padded smem): grid (4, 256), 256 threads
// ---------------------------------------------------------------------------
__global__ __launch_bounds__(256) void stats1(const float* __restrict__ x) {
    __shared__ float rows[76][77];     // 77 stride: conflict-free column reads
    int tc = blockIdx.x, n = blockIdx.y;
    int t0 = tc * 75;
    int tid = threadIdx.x;

    {
        int r = tid / NCH, c = tid - r * NCH;
        const float* xr = x + (size_t)n * TT * NCH;
        for (int i = tid; i < 76 * NCH; i += 256) {
            int t = t0 + r;
            rows[r][c] = (t < TT) ? xr[(size_t)t * NCH + c] : 0.0f;
            c += 31; r += 3; if (c >= NCH) { c -= NCH; r += 1; }
        }
    }
    __syncthreads();

    {
        float* bp = g_bone + (size_t)n * 6 * NP;
        int ch = tid / 75, r = tid - ch * 75;
        int c25 = ch / NV, v = ch - c25 * NV;
        for (int i = tid; i < 75 * 75; i += 256) {
            int ci = v * 3 + c25, pi = c_par[v] * 3 + c25;
            float b = rows[r][ci] - rows[r][pi];
            float d = 0.0f;
            if (t0 + r < TT - 1) d = (rows[r + 1][ci] - rows[r + 1][pi]) - b;
            size_t pidx = (size_t)v * TT + t0 + r;
            bp[(size_t)c25 * NP + pidx]       = b;
            bp[(size_t)(3 + c25) * NP + pidx] = d;
            r += 31; v += 3;
            if (r >= 75) { r -= 75; v += 1; }
            if (v >= NV) { v -= NV; c25 += 1; }
        }
    }

    int g = tid / NCH;
    int ch = tid - g * NCH;
    if (g < 3) {
        int c = ch / NV, v = ch - c * NV;
        int ci = v * 3 + c, pi = c_par[v] * 3 + c;
        float s1 = 0, q1 = 0, s2 = 0, q2 = 0;
        for (int r = g; r < 75; r += 3) {
            float b = rows[r][ci] - rows[r][pi];
            s1 += b; q1 += b * b;
            if (t0 + r < TT - 1) {
                float d = (rows[r + 1][ci] - rows[r + 1][pi]) - b;
                s2 += d; q2 += d * d;
            }
        }
        int idx = (ch * 3 + g) * SBLK + (tc * NN + n);
        g_ps1[idx] = s1; g_pq1[idx] = q1;
        g_ps2[idx] = s2; g_pq2[idx] = q2;
    }
}

__global__ __launch_bounds__(256) void stats2(
    const float* __restrict__ g1, const float* __restrict__ b1,
    const float* __restrict__ g2, const float* __restrict__ b2)
{
    int ch = blockIdx.x;
    int tid = threadIdx.x;
    float s1 = 0, q1 = 0, s2 = 0, q2 = 0;
    for (int g = 0; g < 3; g++) {
        int base = (ch * 3 + g) * SBLK;
        for (int i = tid; i < SBLK; i += 256) {
            s1 += g_ps1[base + i]; q1 += g_pq1[base + i];
            s2 += g_ps2[base + i]; q2 += g_pq2[base + i];
        }
    }
    __shared__ float red[4][256];
    red[0][tid] = s1; red[1][tid] = q1; red[2][tid] = s2; red[3][tid] = q2;
    __syncthreads();
    for (int s = 128; s > 0; s >>= 1) {
        if (tid < s) {
            #pragma unroll
            for (int j = 0; j < 4; j++) red[j][tid] += red[j][tid + s];
        }
        __syncthreads();
    }
    if (tid == 0) {
        const float inv = 1.0f / (float)(NN * TT);
        float m1 = red[0][0] * inv;
        float v1 = red[1][0] * inv - m1 * m1;
        float sc1 = rsqrtf(v1 + 1e-5f) * g1[ch];
        g_sc1[ch] = sc1;
        g_sh1[ch] = b1[ch] - m1 * sc1;
        float m2 = red[2][0] * inv;
        float v2 = red[3][0] * inv - m2 * m2;
        float sc2 = rsqrtf(v2 + 1e-5f) * g2[ch];
        g_sc2[ch] = sc2;
        g_sh2[ch] = b2[ch] - m2 * sc2;
    }
}

// ---------------------------------------------------------------------------
// main kernel (R14 winner): persistent CTAs; m32 x (n32 x 2) warp tile;
// block-wide zy prep; g_bone loads for tile t+GRID prefetched during MMA(t).
// ---------------------------------------------------------------------------
#define ASTR 144                       // A row stride bytes
#define BSTR 144                       // B row stride bytes
#define OFF_A1  0
#define OFF_A2  (OFF_A1 + MTILE * ASTR)
#define OFF_B   (OFF_A2 + MTILE * ASTR)
#define OFF_ZS  (OFF_B + 128 * BSTR)   // z/y staging: 128 x 32 B
#define OFF_BB1 (OFF_ZS + MTILE * 32)
#define OFF_BB2 (OFF_BB1 + 256)
#define SMEM_SZ (OFF_BB2 + 256)

extern __shared__ char smem[];

__global__ __launch_bounds__(THREADS, 2) void main_mma(
    const float* __restrict__ w1a, const float* __restrict__ b1a,
    const float* __restrict__ w1b, const float* __restrict__ b1b,
    const float* __restrict__ w2a, const float* __restrict__ b2a,
    const float* __restrict__ w2b, const float* __restrict__ b2b,
    float* __restrict__ out)
{
    const int tid  = threadIdx.x;
    const int wid  = tid >> 5, lane = tid & 31;

    // ---- one-time staging: fused weight tile (fp16) + biases ----
    for (int i = tid; i < 64 * 64; i += THREADS) {
        int o = i >> 6, h = i & 63;
        *(__half*)(smem + OFF_B + o * BSTR + h * 2)        = __float2half_rn(w1b[i]);
        *(__half*)(smem + OFF_B + (o + 64) * BSTR + h * 2) = __float2half_rn(w2b[i]);
    }
    if (tid < 64) {
        ((float*)(smem + OFF_BB1))[tid] = b1b[tid];
    } else if (tid < 128) {
        ((float*)(smem + OFF_BB2))[tid - 64] = b2b[tid - 64];
    }

    // ---- layer-1 weights in registers (thread owns o-pair = lane) ----
    const int o0 = lane * 2, o1 = lane * 2 + 1;
    const float4 wp1 = make_float4(w1a[o0*3], w1a[o0*3+1], w1a[o0*3+2], b1a[o0]);
    const float4 wq1 = make_float4(w1a[o1*3], w1a[o1*3+1], w1a[o1*3+2], b1a[o1]);
    const float4 wp2 = make_float4(w2a[o0*3], w2a[o0*3+1], w2a[o0*3+2], b2a[o0]);
    const float4 wq2 = make_float4(w2a[o1*3], w2a[o1*3+1], w2a[o1*3+2], b2a[o1]);

    const uint32_t sA1 = s2u(smem + OFF_A1), sA2 = s2u(smem + OFF_A2);
    const uint32_t sB  = s2u(smem + OFF_B);

    // MMA warp tiling: pg = point-group (32 pts), oh = o-half (32 outs)
    const int pg = wid & 3, oh = wid >> 2;
    const uint32_t arow = (uint32_t)(pg * 32 + (lane & 15)) * ASTR + (lane >> 4) * 16;
    const uint32_t brow1 = (uint32_t)(oh * 32 + (lane & 7)) * BSTR + (lane >> 3) * 16;
    const uint32_t brow2 = brow1 + 64 * BSTR;

    // ---- bone prefetch state (tid < 128 only meaningful) ----
    float pc0 = 0, pc1 = 0, pc2 = 0, pd0 = 0, pd1 = 0, pd2 = 0;
    int   pvv = 0;

    // prologue: load bone values for this CTA's first tile
    if (tid < MTILE) {
        const int t0t = blockIdx.x;
        if (t0t < NTILES) {
            const int n0   = t0t / NTPB;
            const int tp00 = (t0t - n0 * NTPB) * MTILE;
            const int pp   = tp00 + tid;
            const int pgc  = (pp < NP) ? pp : (NP - 1);
            pvv = pgc / TT;
            const float* bb = g_bone + (size_t)n0 * 6 * NP + pgc;
            pc0 = bb[0];      pc1 = bb[NP];     pc2 = bb[2 * NP];
            pd0 = bb[3 * NP]; pd1 = bb[4 * NP]; pd2 = bb[5 * NP];
        }
    }

    for (int t = blockIdx.x; t < NTILES; t += GRID_MAIN) {
        const int n   = t / NTPB;
        const int tp0 = (t - n * NTPB) * MTILE;

        __syncthreads();   // staging visible (first iter); A/ZS reuse safety (later)

        // ---- z/y compute from prefetched registers -> ZS ----
        if (tid < MTILE) {
            const int v = pvv;
            float z0 = g_sc1[v]          * pc0 + g_sh1[v];
            float z1 = g_sc1[NV + v]     * pc1 + g_sh1[NV + v];
            float z2 = g_sc1[2 * NV + v] * pc2 + g_sh1[2 * NV + v];
            float y0 = g_sc2[v]          * pd0 + g_sh2[v];
            float y1 = g_sc2[NV + v]     * pd1 + g_sh2[NV + v];
            float y2 = g_sc2[2 * NV + v] * pd2 + g_sh2[2 * NV + v];
            *(float4*)(smem + OFF_ZS + tid * 32)      = make_float4(z0, z1, z2, 0.f);
            *(float4*)(smem + OFF_ZS + tid * 32 + 16) = make_float4(y0, y1, y2, 0.f);
        }
        __syncthreads();

        // ---- H phase: thread = o-pair (lane), 16 points per warp ----
        #pragma unroll
        for (int i = 0; i < 16; i++) {
            const int p = wid * 16 + i;
            float4 z = *(const float4*)(smem + OFF_ZS + p * 32);
            float4 y = *(const float4*)(smem + OFF_ZS + p * 32 + 16);
            float h0 = fmaxf(fmaf(wp1.x, z.x, fmaf(wp1.y, z.y, fmaf(wp1.z, z.z, wp1.w))), 0.0f);
            float h1 = fmaxf(fmaf(wq1.x, z.x, fmaf(wq1.y, z.y, fmaf(wq1.z, z.z, wq1.w))), 0.0f);
            uint32_t pk;
            asm("cvt.rn.f16x2.f32 %0, %1, %2;" : "=r"(pk) : "f"(h1), "f"(h0));
            *(uint32_t*)(smem + OFF_A1 + p * ASTR + lane * 4) = pk;

            float g0 = fmaxf(fmaf(wp2.x, y.x, fmaf(wp2.y, y.y, fmaf(wp2.z, y.z, wp2.w))), 0.0f);
            float g1 = fmaxf(fmaf(wq2.x, y.x, fmaf(wq2.y, y.y, fmaf(wq2.z, y.z, wq2.w))), 0.0f);
            asm("cvt.rn.f16x2.f32 %0, %1, %2;" : "=r"(pk) : "f"(g1), "f"(g0));
            *(uint32_t*)(smem + OFF_A2 + p * ASTR + lane * 4) = pk;
        }
        __syncthreads();   // A tiles ready; all ZS reads done

        // ---- prefetch NEXT tile's bone values (in flight through MMA) ----
        if (tid < MTILE) {
            const int tn = t + GRID_MAIN;
            if (tn < NTILES) {
                const int nn_  = tn / NTPB;
                const int tpn  = (tn - nn_ * NTPB) * MTILE;
                const int pp   = tpn + tid;
                const int pgc  = (pp < NP) ? pp : (NP - 1);
                pvv = pgc / TT;
                const float* bb = g_bone + (size_t)nn_ * 6 * NP + pgc;
                pc0 = bb[0];      pc1 = bb[NP];     pc2 = bb[2 * NP];
                pd0 = bb[3 * NP]; pd1 = bb[4 * NP]; pd2 = bb[5 * NP];
            }
        }

        // ---- MMA phase: warp = m32 x n32 x 2 branches ----
        float a1[2][4][4], a2[2][4][4];
        #pragma unroll
        for (int mt = 0; mt < 2; mt++)
            #pragma unroll
            for (int nt = 0; nt < 4; nt++)
                #pragma unroll
                for (int q = 0; q < 4; q++) { a1[mt][nt][q] = 0.f; a2[mt][nt][q] = 0.f; }

        #pragma unroll
        for (int kcp = 0; kcp < 2; kcp++) {
            uint32_t af[2][2][4];
            // ---- branch 1 ----
            #pragma unroll
            for (int mt = 0; mt < 2; mt++)
                #pragma unroll
                for (int k2 = 0; k2 < 2; k2++)
                    ldsm4(af[mt][k2], sA1 + arow + (uint32_t)mt * 16 * ASTR + (kcp * 2 + k2) * 32);
            #pragma unroll
            for (int nt = 0; nt < 4; nt++) {
                uint32_t bf[4];
                ldsm4(bf, sB + brow1 + (uint32_t)nt * 8 * BSTR + kcp * 64);
                #pragma unroll
                for (int k2 = 0; k2 < 2; k2++)
                    #pragma unroll
                    for (int mt = 0; mt < 2; mt++)
                        mma16816(a1[mt][nt], af[mt][k2], bf[2*k2], bf[2*k2+1]);
            }
            // ---- branch 2 ----
            #pragma unroll
            for (int mt = 0; mt < 2; mt++)
                #pragma unroll
                for (int k2 = 0; k2 < 2; k2++)
                    ldsm4(af[mt][k2], sA2 + arow + (uint32_t)mt * 16 * ASTR + (kcp * 2 + k2) * 32);
            #pragma unroll
            for (int nt = 0; nt < 4; nt++) {
                uint32_t bf[4];
                ldsm4(bf, sB + brow2 + (uint32_t)nt * 8 * BSTR + kcp * 64);
                #pragma unroll
                for (int k2 = 0; k2 < 2; k2++)
                    #pragma unroll
                    for (int mt = 0; mt < 2; mt++)
                        mma16816(a2[mt][nt], af[mt][k2], bf[2*k2], bf[2*k2+1]);
            }
        }

        // ---- epilogue: bias + relu + sum, direct STG ----
        {
            const float* bb1 = (const float*)(smem + OFF_BB1);
            const float* bb2 = (const float*)(smem + OFF_BB2);
            float* ob = out + (size_t)n * 64 * NP;
            #pragma unroll
            for (int mt = 0; mt < 2; mt++) {
                const int r0 = tp0 + pg * 32 + mt * 16 + (lane >> 2);
                #pragma unroll
                for (int nt = 0; nt < 4; nt++) {
                    const int oc = oh * 32 + nt * 8 + (lane & 3) * 2;
                    float u0 = bb1[oc], u1 = bb1[oc + 1];
                    float w0 = bb2[oc], w1 = bb2[oc + 1];
                    if (r0 < NP) {
                        ob[(size_t)oc * NP + r0]       = fmaxf(a1[mt][nt][0] + u0, 0.f) + fmaxf(a2[mt][nt][0] + w0, 0.f);
                        ob[(size_t)(oc + 1) * NP + r0] = fmaxf(a1[mt][nt][1] + u1, 0.f) + fmaxf(a2[mt][nt][1] + w1, 0.f);
                    }
                    if (r0 + 8 < NP) {
                        ob[(size_t)oc * NP + r0 + 8]       = fmaxf(a1[mt][nt][2] + u0, 0.f) + fmaxf(a2[mt][nt][2] + w0, 0.f);
                        ob[(size_t)(oc + 1) * NP + r0 + 8] = fmaxf(a1[mt][nt][3] + u1, 0.f) + fmaxf(a2[mt][nt][3] + w1, 0.f);
                    }
                }
            }
        }
    }
}

// ---------------------------------------------------------------------------
extern "C" void kernel_launch(void* const* d_in, const int* in_sizes, int n_in,
                              void* d_out, int out_size)
{
    const float* x   = (const float*)d_in[0];
    const float* g1  = (const float*)d_in[1];
    const float* b1g = (const float*)d_in[2];
    const float* w1a = (const float*)d_in[3];
    const float* b1a = (const float*)d_in[4];
    const float* w1b = (const float*)d_in[5];
    const float* b1b = (const float*)d_in[6];
    const float* g2  = (const float*)d_in[7];
    const float* b2g = (const float*)d_in[8];
    const float* w2a = (const float*)d_in[9];
    const float* b2a = (const float*)d_in[10];
    const float* w2b = (const float*)d_in[11];
    const float* b2b = (const float*)d_in[12];
    float* out = (float*)d_out;

    stats1<<<dim3(4, NN), 256>>>(x);
    stats2<<<NCH, 256>>>(g1, b1g, g2, b2g);

    cudaFuncSetAttribute(main_mma, cudaFuncAttributeMaxDynamicSharedMemorySize, SMEM_SZ);
    main_mma<<<GRID_MAIN, THREADS, SMEM_SZ>>>(
        w1a, b1a, w1b, b1b, w2a, b2a, w2b, b2b, out);
}